// round 11
// baseline (speedup 1.0000x reference)
#include <cuda_runtime.h>
#include <cuda_bf16.h>
#include <cstdint>

// ---------------------------------------------------------------------------
// Multi-scale residual VQ (VectorQuantizer2): B=64, C=32, H=W=16, vocab=4096
// scales pn = {1,2,3,4,5,6,8,10,13,16}
//
// One 2-CTA cluster per batch image; codebook split 2048/2048 across the pair.
// 256 threads/CTA. Register tile per thread: 16 rows x 4 codes = 32
// independent fma.rn.f32x2 chains. Per channel k: 1 LDS.128 (two adjacent
// code-pairs {e_2p,e_2p+1}) + 8 broadcast LDS.128 (16 rows of {-2z,-2z}) +
// 32 FFMA2 (76% FFMA2 mix, no MOVs). Codebook staged in two 1024-code /
// 128 KB smem chunks; z-dup rebuilt per 16-row block (4 KB).
// Each f32x2 half reproduces the reference's sequential ascending-c FMA chain
// bit-exactly. Argmin: in-lane min-of-4 (ascending code), redux+ballot
// (lane order == code order), smem atomicMin on (biased-dist,idx) u64 keys
// (lowest index on ties), cross-CTA merge via global scratch + barrier.cluster.
// ---------------------------------------------------------------------------

#define NSCALES 10
__device__ __constant__ int c_pns[NSCALES] = {1, 2, 3, 4, 5, 6, 8, 10, 13, 16};

// device scratch (static globals -- no allocation)
__device__ unsigned long long g_epair[32 * 2048]; // [c][pair]={emb[2p][c],emb[2p+1][c]}
__device__ float  g_esq[4096];                    // ||e||^2 (rounded squares, seq sum)
__device__ unsigned long long g_key[64 * 512];    // per-batch, per-rank best keys

// ---------------- shared memory (225584 B total) ----------------
struct SMem {
    unsigned long long echunk[32 * 512]; // 128 KB  [k][pair-in-chunk]; aliased as tmpf
    unsigned long long zdupb[32 * 16];   // 4 KB    [k][row-in-block] {-2z,-2z}
    float frest[8192];                   // [h][w][c]
    float fhat[8192];                    // [h][w][c]
    float zbuf[5440];                    // z rows / gathered codes (N<=169 non-last)
    unsigned long long bkey[256];        // running best (biased dist, idx) per row
    float zsq[256];                      // per-row ||z||^2
    float wu[256];                       // upsample weights [k_in*16 + i_out]
    int   idxs[256];                     // merged final indices
};

__device__ __forceinline__ void cluster_sync_() {
    asm volatile("barrier.cluster.arrive.aligned;\n\t"
                 "barrier.cluster.wait.aligned;\n" ::: "memory");
}

__device__ __forceinline__ void ffma2(unsigned long long& acc,
                                      unsigned long long a, unsigned long long b) {
    asm("fma.rn.f32x2 %0, %1, %2, %0;" : "+l"(acc) : "l"(a), "l"(b));
}
__device__ __forceinline__ unsigned long long pack2(float lo, float hi) {
    unsigned long long d;
    unsigned a = __float_as_uint(lo), b = __float_as_uint(hi);
    asm("mov.b64 %0, {%1, %2};" : "=l"(d) : "r"(a), "r"(b));
    return d;
}
__device__ __forceinline__ void unpack2(unsigned long long v, float& lo, float& hi) {
    unsigned a, b;
    asm("mov.b64 {%0, %1}, %2;" : "=r"(a), "=r"(b) : "l"(v));
    lo = __uint_as_float(a);
    hi = __uint_as_float(b);
}
__device__ __forceinline__ unsigned redux_min_u32(unsigned v) {
    unsigned r;
    asm("redux.sync.min.u32 %0, %1, 0xffffffff;" : "=r"(r) : "r"(v));
    return r;
}

// jax _fill_keys_cubic_kernel (a = -0.5), each op rounded separately
__device__ __forceinline__ float keys_w(float x) {
    float w;
    if (x < 1.0f) {
        float t = __fmul_rn(1.5f, x);
        t = __fsub_rn(t, 2.5f);
        t = __fmul_rn(t, x);
        t = __fmul_rn(t, x);
        w = __fadd_rn(t, 1.0f);
    } else if (x < 2.0f) {
        float t = __fmul_rn(-0.5f, x);
        t = __fadd_rn(t, 2.5f);
        t = __fmul_rn(t, x);
        t = __fsub_rn(t, 4.0f);
        t = __fmul_rn(t, x);
        w = __fadd_rn(t, 2.0f);
    } else {
        w = 0.0f;
    }
    return w;
}

// ---------------------------------------------------------------------------
// prep: build paired codebook layout + esq
// ---------------------------------------------------------------------------
__global__ void vq_prep_kernel(const float* __restrict__ emb) {
    int p = blockIdx.x * blockDim.x + threadIdx.x;   // pair index 0..2047
    if (p >= 2048) return;
    const float* r0 = emb + (2 * p) * 32;
    const float* r1 = emb + (2 * p + 1) * 32;
    float a0 = 0.0f, a1 = 0.0f;
#pragma unroll
    for (int c = 0; c < 32; c++) {
        float x0 = r0[c], x1 = r1[c];
        a0 = __fadd_rn(a0, __fmul_rn(x0, x0));
        a1 = __fadd_rn(a1, __fmul_rn(x1, x1));
        g_epair[c * 2048 + p] = pack2(x0, x1);
    }
    g_esq[2 * p] = a0;
    g_esq[2 * p + 1] = a1;
}

// ---------------------------------------------------------------------------
// main kernel: one cluster (2 CTAs) per batch image, 256 threads
// ---------------------------------------------------------------------------
extern "C" __global__ void __cluster_dims__(2, 1, 1) __launch_bounds__(256, 1)
vq_main_kernel(const float* __restrict__ f, const float* __restrict__ emb,
               float* __restrict__ out) {
    extern __shared__ char smem_raw[];
    SMem* sm = reinterpret_cast<SMem*>(smem_raw);

    const int tid = threadIdx.x;
    const int lane = tid & 31;
    const int wid = tid >> 5;
    const int b = blockIdx.x >> 1;
    const int rank = blockIdx.x & 1;

    // init: frest = transpose(f) (BCHW -> HWC), fhat = 0
    for (int t = tid; t < 8192; t += 256) {
        int c = t & 31;
        int ij = t >> 5;
        sm->frest[t] = f[(b * 32 + c) * 256 + ij];
        sm->fhat[t] = 0.0f;
    }
    __syncthreads();

    float* tmpf = reinterpret_cast<float*>(sm->echunk);  // scratch alias (<=26KB use)

    for (int si = 0; si < NSCALES; si++) {
        const int pn = c_pns[si];
        const int N = pn * pn;
        const bool last = (si == NSCALES - 1);

        // ---------- z = area pool of frest (last scale: z aliases frest) ----------
        if (!last) {
            const int n1 = pn * 16 * 32;
            for (int t = tid; t < n1; t += 256) {
                int c = t & 31, w = (t >> 5) & 15, p = t >> 9;
                int sh = (p * 16) / pn;
                int eh = ((p + 1) * 16 + pn - 1) / pn;
                float wt = (float)(1.0 / (double)(eh - sh));
                float acc = 0.0f;
                for (int h = sh; h < eh; h++)
                    acc = fmaf(wt, sm->frest[(h * 16 + w) * 32 + c], acc);
                tmpf[t] = acc;
            }
            __syncthreads();
            const int n2 = N * 32;
            for (int t = tid; t < n2; t += 256) {
                int c = t & 31, q = (t >> 5) % pn, p = (t >> 5) / pn;
                int sw = (q * 16) / pn;
                int ew = ((q + 1) * 16 + pn - 1) / pn;
                float wt = (float)(1.0 / (double)(ew - sw));
                float acc = 0.0f;
                for (int w = sw; w < ew; w++)
                    acc = fmaf(wt, tmpf[p * 512 + w * 32 + c], acc);
                sm->zbuf[t] = acc;
            }
            __syncthreads();
        }
        const float* zp = last ? sm->frest : sm->zbuf;

        // ---------- zsq (rounded squares, sequential ascending sum) ----------
        if (tid < N) {
            float acc = 0.0f;
            for (int c = 0; c < 32; c++) {
                float z = zp[tid * 32 + c];
                acc = __fadd_rn(acc, __fmul_rn(z, z));
            }
            sm->zsq[tid] = acc;
        }
        for (int t = tid; t < N; t += 256) sm->bkey[t] = 0xFFFFFFFFFFFFFFFFull;
        __syncthreads();

        // ---------- distance + argmin over this CTA's 2048-code half ----------
        const int nblk = (N + 15) >> 4;
        for (int chunk = 0; chunk < 2; chunk++) {
            const int pbase = rank * 1024 + chunk * 512;       // global pair base
            // stage 1024 codes = 512 pairs x 32 ch (128 KB)
            for (int t = tid; t < 8192; t += 256) {
                int k = t >> 8, p2 = t & 255;
                *reinterpret_cast<ulonglong2*>(&sm->echunk[k * 512 + p2 * 2]) =
                    *reinterpret_cast<const ulonglong2*>(
                        &g_epair[k * 2048 + pbase + p2 * 2]);
            }
            const int c0 = 2 * pbase + wid * 128 + lane * 4;   // my 4 codes
            const float4 eq = *reinterpret_cast<const float4*>(g_esq + c0);
            const int ep = wid * 64 + lane * 2;                // my pair offset
            __syncthreads();

            for (int blk = 0; blk < nblk; blk++) {
                __syncthreads();   // previous block's zdupb readers done
                // build {-2z,-2z} for this 16-row block, layout [k][r]
                for (int t = tid; t < 512; t += 256) {
                    int k = t >> 4, r = t & 15;
                    int row = blk * 16 + r;
                    if (row >= N) row = N - 1;
                    float m = __fmul_rn(-2.0f, zp[row * 32 + k]);   // exact *(-2)
                    sm->zdupb[k * 16 + r] = pack2(m, m);
                }
                __syncthreads();

                unsigned long long acc0[16], acc1[16];
#pragma unroll
                for (int i = 0; i < 16; i++) { acc0[i] = 0ull; acc1[i] = 0ull; }

#pragma unroll
                for (int k = 0; k < 32; k++) {
                    ulonglong2 e = *reinterpret_cast<const ulonglong2*>(
                        &sm->echunk[k * 512 + ep]);
                    ulonglong2 zv[8];
#pragma unroll
                    for (int q = 0; q < 8; q++)
                        zv[q] = *reinterpret_cast<const ulonglong2*>(
                            &sm->zdupb[k * 16 + q * 2]);
#pragma unroll
                    for (int q = 0; q < 8; q++) {
                        ffma2(acc0[2 * q],     zv[q].x, e.x);
                        ffma2(acc1[2 * q],     zv[q].x, e.y);
                        ffma2(acc0[2 * q + 1], zv[q].y, e.x);
                        ffma2(acc1[2 * q + 1], zv[q].y, e.y);
                    }
                }

                // epilogue: per-row best of my 4 codes -> warp -> smem atomicMin
#pragma unroll
                for (int i = 0; i < 16; i++) {
                    int row = blk * 16 + i;
                    if (row < N) {
                        float zs = sm->zsq[row];
                        float d0, d1, d2, d3;
                        unpack2(acc0[i], d0, d1);   // codes c0, c0+1
                        unpack2(acc1[i], d2, d3);   // codes c0+2, c0+3
                        d0 = __fadd_rn(__fadd_rn(zs, eq.x), d0);
                        d1 = __fadd_rn(__fadd_rn(zs, eq.y), d1);
                        d2 = __fadd_rn(__fadd_rn(zs, eq.z), d2);
                        d3 = __fadd_rn(__fadd_rn(zs, eq.w), d3);
                        float best = d0;
                        int bi = 0;
                        if (d1 < best) { best = d1; bi = 1; }
                        if (d2 < best) { best = d2; bi = 2; }
                        if (d3 < best) { best = d3; bi = 3; }
                        unsigned ub = __float_as_uint(best);
                        ub = (ub & 0x80000000u) ? ~ub : (ub ^ 0x80000000u);
                        unsigned mn = redux_min_u32(ub);
                        unsigned msk = __ballot_sync(0xffffffffu, ub == mn);
                        if (lane == (__ffs(msk) - 1))
                            atomicMin(&sm->bkey[row],
                                      ((unsigned long long)ub << 32) |
                                          (unsigned)(c0 + bi));
                    }
                }
            }
            __syncthreads();   // all atomics done; echunk free for restage
        }

        // ---------- merge halves across the CTA pair ----------
        for (int t = tid; t < N; t += 256)
            g_key[(b << 9) + (rank << 8) + t] = sm->bkey[t];
        cluster_sync_();   // release/acquire covers gmem at cluster scope
        for (int t = tid; t < N; t += 256) {
            unsigned long long k0 = g_key[(b << 9) + t];
            unsigned long long k1 = g_key[(b << 9) + 256 + t];
            sm->idxs[t] = (int)((k0 < k1 ? k0 : k1) & 0xFFFFFFFFu);
        }
        __syncthreads();

        // ---------- gather h = emb[idx], upsample, update ----------
        if (last) {
            for (int t = tid; t < 8192; t += 256)
                sm->fhat[t] = __fadd_rn(sm->fhat[t],
                                        emb[sm->idxs[t >> 5] * 32 + (t & 31)]);
        } else {
            for (int t = tid; t < N * 32; t += 256)
                sm->zbuf[t] = emb[sm->idxs[t >> 5] * 32 + (t & 31)];
            // weights: compute_weight_mat(pn, 16, 16/pn, 0, keys_cubic, True)
            if (tid < 16) {
                const int i = tid;
                double scl_d = 16.0 / (double)pn;
                float inv = (float)(1.0 / scl_d);
                float sf = __fsub_rn(__fmul_rn(__fadd_rn((float)i, 0.5f), inv), 0.5f);
                float tot = 0.0f;
                for (int k = 0; k < pn; k++) {
                    float x = fabsf(__fsub_rn(sf, (float)k));
                    tot = __fadd_rn(tot, keys_w(x));
                }
                for (int k = 0; k < pn; k++) {
                    float x = fabsf(__fsub_rn(sf, (float)k));
                    sm->wu[k * 16 + i] = __fdiv_rn(keys_w(x), tot);
                }
            }
            __syncthreads();
            // pass 1: contract input-h (k ascending) -> tmpf
            const int n1 = 16 * pn * 32;
            for (int t = tid; t < n1; t += 256) {
                int c = t & 31, kw = (t >> 5) % pn, i = (t >> 5) / pn;
                float acc = 0.0f;
                for (int k = 0; k < pn; k++)
                    acc = fmaf(sm->wu[k * 16 + i], sm->zbuf[(k * pn + kw) * 32 + c], acc);
                tmpf[t] = acc;   // layout (i*pn + kw)*32 + c
            }
            __syncthreads();
            // pass 2: contract input-w, then update fhat/frest
            for (int t = tid; t < 8192; t += 256) {
                int c = t & 31, j = (t >> 5) & 15, i = t >> 9;
                float acc = 0.0f;
                for (int k = 0; k < pn; k++)
                    acc = fmaf(sm->wu[k * 16 + j], tmpf[(i * pn + k) * 32 + c], acc);
                sm->fhat[t] = __fadd_rn(sm->fhat[t], acc);
                sm->frest[t] = __fsub_rn(sm->frest[t], acc);
            }
        }

        cluster_sync_();   // peer done with g_key before next-scale overwrite
        __syncthreads();
    }

    // ---------- write output: BHWC -> BCHW ----------
    for (int t = tid; t < 4096; t += 256) {
        int c = rank * 16 + (t >> 8);
        int ij = t & 255;
        out[(b * 32 + c) * 256 + ij] = sm->fhat[ij * 32 + c];
    }
}

// ---------------------------------------------------------------------------
extern "C" void kernel_launch(void* const* d_in, const int* in_sizes, int n_in,
                              void* d_out, int out_size) {
    (void)in_sizes; (void)n_in; (void)out_size;
    const float* f = (const float*)d_in[0];     // [64,32,16,16] f32
    const float* emb = (const float*)d_in[1];   // [4096,32] f32
    float* out = (float*)d_out;                 // [64,32,16,16] f32

    static int smem_set = 0;
    if (!smem_set) {
        cudaFuncSetAttribute(vq_main_kernel,
                             cudaFuncAttributeMaxDynamicSharedMemorySize,
                             (int)sizeof(SMem));
        smem_set = 1;
    }

    vq_prep_kernel<<<8, 256>>>(emb);
    vq_main_kernel<<<128, 256, sizeof(SMem)>>>(f, emb, out);
}

// round 13
// speedup vs baseline: 1.1376x; 1.1376x over previous
#include <cuda_runtime.h>
#include <cuda_bf16.h>
#include <cstdint>

// ---------------------------------------------------------------------------
// Multi-scale residual VQ (VectorQuantizer2): B=64, C=32, H=W=16, vocab=4096
// scales pn = {1,2,3,4,5,6,8,10,13,16}
//
// One 2-CTA cluster per batch image; codebook split 2048/2048 across the pair.
// 512 threads/CTA (16 warps/SM). Codebook staged as plain [k][code] floats in
// 1024-code / 128 KB smem chunks; a float4 LDS of 4 consecutive codes IS two
// natural f32x2 pairs -> no duplication MOVs on the e side. z side pre-dup'd
// {-2z,-2z} per 16-row block (4 KB). Thread tile 8 rows x 4 codes = 16
// independent fma.rn.f32x2 chains; per channel k: 1 LDS.128 (e) + 4 broadcast
// LDS.128 (z) + 16 FFMA2. 16 warps = 8 code-groups x 2 row-groups.
// Each f32x2 half reproduces the reference's sequential ascending-c FMA chain
// bit-exactly. Argmin: in-thread min-of-4 (ascending code), redux+ballot
// (lane order == code order), smem atomicMin on (biased-dist,idx) u64 keys,
// cross-CTA merge via global scratch + barrier.cluster.
// ---------------------------------------------------------------------------

#define NSCALES 10
__device__ __constant__ int c_pns[NSCALES] = {1, 2, 3, 4, 5, 6, 8, 10, 13, 16};

// device scratch (static globals -- no allocation)
__device__ float g_ecb[32 * 4096];               // [c][code] transposed codebook
__device__ float g_esq[4096];                    // ||e||^2 (rounded squares, seq sum)
__device__ unsigned long long g_key[64 * 512];   // per-batch, per-rank best keys

// ---------------- shared memory (227584 B) ----------------
struct SMem {
    float echunk[32 * 1024];             // 128 KB [k][code]; aliased as tmpf scratch
    unsigned long long zdupb[32 * 16];   // 4 KB   [k][row-in-block] {-2z,-2z}
    float frest[8192];                   // [h][w][c]
    float fhat[8192];                    // [h][w][c]
    float zbuf[5440];                    // z rows / gathered codes (N<=169 non-last)
    unsigned long long bkey[256];        // running best (biased dist, idx) per row
    float zsq[256];                      // per-row ||z||^2
    float wu[256];                       // upsample weights [k_in*16 + i_out]
    int   idxs[256];                     // merged final indices
};

__device__ __forceinline__ void cluster_sync_() {
    asm volatile("barrier.cluster.arrive.aligned;\n\t"
                 "barrier.cluster.wait.aligned;\n" ::: "memory");
}

__device__ __forceinline__ void ffma2(unsigned long long& acc,
                                      unsigned long long a, unsigned long long b) {
    asm("fma.rn.f32x2 %0, %1, %2, %0;" : "+l"(acc) : "l"(a), "l"(b));
}
__device__ __forceinline__ unsigned long long pack2(float lo, float hi) {
    unsigned long long d;
    unsigned a = __float_as_uint(lo), b = __float_as_uint(hi);
    asm("mov.b64 %0, {%1, %2};" : "=l"(d) : "r"(a), "r"(b));
    return d;
}
__device__ __forceinline__ void unpack2(unsigned long long v, float& lo, float& hi) {
    unsigned a, b;
    asm("mov.b64 {%0, %1}, %2;" : "=r"(a), "=r"(b) : "l"(v));
    lo = __uint_as_float(a);
    hi = __uint_as_float(b);
}
__device__ __forceinline__ unsigned redux_min_u32(unsigned v) {
    unsigned r;
    asm("redux.sync.min.u32 %0, %1, 0xffffffff;" : "=r"(r) : "r"(v));
    return r;
}

// jax _fill_keys_cubic_kernel (a = -0.5), each op rounded separately
__device__ __forceinline__ float keys_w(float x) {
    float w;
    if (x < 1.0f) {
        float t = __fmul_rn(1.5f, x);
        t = __fsub_rn(t, 2.5f);
        t = __fmul_rn(t, x);
        t = __fmul_rn(t, x);
        w = __fadd_rn(t, 1.0f);
    } else if (x < 2.0f) {
        float t = __fmul_rn(-0.5f, x);
        t = __fadd_rn(t, 2.5f);
        t = __fmul_rn(t, x);
        t = __fsub_rn(t, 4.0f);
        t = __fmul_rn(t, x);
        w = __fadd_rn(t, 2.0f);
    } else {
        w = 0.0f;
    }
    return w;
}

// ---------------------------------------------------------------------------
// prep: transpose codebook to [c][code] + esq
// ---------------------------------------------------------------------------
__global__ void vq_prep_kernel(const float* __restrict__ emb) {
    int j = blockIdx.x * blockDim.x + threadIdx.x;
    if (j >= 4096) return;
    float acc = 0.0f;
#pragma unroll
    for (int c = 0; c < 32; c++) {
        float x = emb[j * 32 + c];
        acc = __fadd_rn(acc, __fmul_rn(x, x));
        g_ecb[c * 4096 + j] = x;
    }
    g_esq[j] = acc;
}

// ---------------------------------------------------------------------------
// main kernel: one cluster (2 CTAs) per batch image, 512 threads
// ---------------------------------------------------------------------------
extern "C" __global__ void __cluster_dims__(2, 1, 1) __launch_bounds__(512, 1)
vq_main_kernel(const float* __restrict__ f, const float* __restrict__ emb,
               float* __restrict__ out) {
    extern __shared__ char smem_raw[];
    SMem* sm = reinterpret_cast<SMem*>(smem_raw);

    const int tid = threadIdx.x;
    const int lane = tid & 31;
    const int wid = tid >> 5;
    const int b = blockIdx.x >> 1;
    const int rank = blockIdx.x & 1;
    const int cgrp = wid & 7;    // code group (8 x 128 codes = 1024)
    const int rgrp = wid >> 3;   // row group (2 x 8 rows = 16-row block)

    // init: frest = transpose(f) (BCHW -> HWC), fhat = 0
    for (int t = tid; t < 8192; t += 512) {
        int c = t & 31;
        int ij = t >> 5;
        sm->frest[t] = f[(b * 32 + c) * 256 + ij];
        sm->fhat[t] = 0.0f;
    }
    __syncthreads();

    float* tmpf = sm->echunk;   // scratch alias (<= 26 KB use)

    for (int si = 0; si < NSCALES; si++) {
        const int pn = c_pns[si];
        const int N = pn * pn;
        const bool last = (si == NSCALES - 1);

        // ---------- z = area pool of frest (last scale: z aliases frest) ----------
        if (!last) {
            const int n1 = pn * 16 * 32;
            for (int t = tid; t < n1; t += 512) {
                int c = t & 31, w = (t >> 5) & 15, p = t >> 9;
                int sh = (p * 16) / pn;
                int eh = ((p + 1) * 16 + pn - 1) / pn;
                float wt = (float)(1.0 / (double)(eh - sh));
                float acc = 0.0f;
                for (int h = sh; h < eh; h++)
                    acc = fmaf(wt, sm->frest[(h * 16 + w) * 32 + c], acc);
                tmpf[t] = acc;
            }
            __syncthreads();
            const int n2 = N * 32;
            for (int t = tid; t < n2; t += 512) {
                int c = t & 31, q = (t >> 5) % pn, p = (t >> 5) / pn;
                int sw = (q * 16) / pn;
                int ew = ((q + 1) * 16 + pn - 1) / pn;
                float wt = (float)(1.0 / (double)(ew - sw));
                float acc = 0.0f;
                for (int w = sw; w < ew; w++)
                    acc = fmaf(wt, tmpf[p * 512 + w * 32 + c], acc);
                sm->zbuf[t] = acc;
            }
            __syncthreads();
        }
        const float* zp = last ? sm->frest : sm->zbuf;

        // ---------- zsq (rounded squares, sequential ascending sum) ----------
        if (tid < N) {
            float acc = 0.0f;
            for (int c = 0; c < 32; c++) {
                float z = zp[tid * 32 + c];
                acc = __fadd_rn(acc, __fmul_rn(z, z));
            }
            sm->zsq[tid] = acc;
        }
        for (int t = tid; t < N; t += 512) sm->bkey[t] = 0xFFFFFFFFFFFFFFFFull;
        __syncthreads();

        // ---------- distance + argmin over this CTA's 2048-code half ----------
        const int nblk = (N + 15) >> 4;
        for (int chunk = 0; chunk < 2; chunk++) {
            const int cbase = rank * 2048 + chunk * 1024;
            // stage 1024 codes x 32 ch (128 KB), [k][code]
            {
                float4* dst = reinterpret_cast<float4*>(sm->echunk);
                for (int t = tid; t < 8192; t += 512) {
                    int k = t >> 8, j4 = t & 255;
                    dst[k * 256 + j4] = *reinterpret_cast<const float4*>(
                        &g_ecb[k * 4096 + cbase + j4 * 4]);
                }
            }
            const int c0 = cgrp * 128 + lane * 4;   // code offset within chunk
            const float4 eq = *reinterpret_cast<const float4*>(g_esq + cbase + c0);
            __syncthreads();

            for (int blk = 0; blk < nblk; blk++) {
                // build {-2z,-2z} for this 16-row block, layout [k][r]
                {
                    int k = tid >> 4, r = tid & 15;
                    int row = blk * 16 + r;
                    if (row >= N) row = N - 1;
                    float m = __fmul_rn(-2.0f, zp[row * 32 + k]);   // exact *(-2)
                    sm->zdupb[k * 16 + r] = pack2(m, m);
                }
                __syncthreads();

                unsigned long long acc[16];
#pragma unroll
                for (int i = 0; i < 16; i++) acc[i] = 0ull;

#pragma unroll
                for (int k = 0; k < 32; k++) {
                    // two natural code-pairs from one float4-equivalent load
                    ulonglong2 epr = *reinterpret_cast<const ulonglong2*>(
                        &sm->echunk[k * 1024 + c0]);
                    // 8 rows of {-2z,-2z} (broadcast)
                    const ulonglong2* zb = reinterpret_cast<const ulonglong2*>(
                        &sm->zdupb[k * 16 + rgrp * 8]);
                    ulonglong2 zv0 = zb[0];
                    ulonglong2 zv1 = zb[1];
                    ulonglong2 zv2 = zb[2];
                    ulonglong2 zv3 = zb[3];
                    ffma2(acc[0],  zv0.x, epr.x);
                    ffma2(acc[1],  zv0.x, epr.y);
                    ffma2(acc[2],  zv0.y, epr.x);
                    ffma2(acc[3],  zv0.y, epr.y);
                    ffma2(acc[4],  zv1.x, epr.x);
                    ffma2(acc[5],  zv1.x, epr.y);
                    ffma2(acc[6],  zv1.y, epr.x);
                    ffma2(acc[7],  zv1.y, epr.y);
                    ffma2(acc[8],  zv2.x, epr.x);
                    ffma2(acc[9],  zv2.x, epr.y);
                    ffma2(acc[10], zv2.y, epr.x);
                    ffma2(acc[11], zv2.y, epr.y);
                    ffma2(acc[12], zv3.x, epr.x);
                    ffma2(acc[13], zv3.x, epr.y);
                    ffma2(acc[14], zv3.y, epr.x);
                    ffma2(acc[15], zv3.y, epr.y);
                }

                // epilogue: 8 rows, best of my 4 codes -> warp -> smem atomicMin
#pragma unroll
                for (int r8 = 0; r8 < 8; r8++) {
                    int row = blk * 16 + rgrp * 8 + r8;
                    if (row < N) {
                        const int q = r8 >> 1, s = r8 & 1;
                        float zs = sm->zsq[row];
                        float d0, d1, d2, d3;
                        unpack2(acc[4 * q + 2 * s + 0], d0, d1);  // codes c0, c0+1
                        unpack2(acc[4 * q + 2 * s + 1], d2, d3);  // codes c0+2, c0+3
                        d0 = __fadd_rn(__fadd_rn(zs, eq.x), d0);
                        d1 = __fadd_rn(__fadd_rn(zs, eq.y), d1);
                        d2 = __fadd_rn(__fadd_rn(zs, eq.z), d2);
                        d3 = __fadd_rn(__fadd_rn(zs, eq.w), d3);
                        float best = d0;
                        int bi = 0;
                        if (d1 < best) { best = d1; bi = 1; }
                        if (d2 < best) { best = d2; bi = 2; }
                        if (d3 < best) { best = d3; bi = 3; }
                        unsigned ub = __float_as_uint(best);
                        ub = (ub & 0x80000000u) ? ~ub : (ub ^ 0x80000000u);
                        unsigned mn = redux_min_u32(ub);
                        unsigned msk = __ballot_sync(0xffffffffu, ub == mn);
                        if (lane == (__ffs(msk) - 1))
                            atomicMin(&sm->bkey[row],
                                      ((unsigned long long)ub << 32) |
                                          (unsigned)(cbase + c0 + bi));
                    }
                }
                __syncthreads();   // block done before zdupb rebuild
            }
            __syncthreads();   // all atomics done; echunk free for restage
        }

        // ---------- merge halves across the CTA pair ----------
        for (int t = tid; t < N; t += 512)
            g_key[(b << 9) + (rank << 8) + t] = sm->bkey[t];
        cluster_sync_();   // release/acquire covers gmem at cluster scope
        for (int t = tid; t < N; t += 512) {
            unsigned long long k0 = g_key[(b << 9) + t];
            unsigned long long k1 = g_key[(b << 9) + 256 + t];
            sm->idxs[t] = (int)((k0 < k1 ? k0 : k1) & 0xFFFFFFFFu);
        }
        __syncthreads();

        // ---------- gather h = emb[idx], upsample, update ----------
        if (last) {
            for (int t = tid; t < 8192; t += 512)
                sm->fhat[t] = __fadd_rn(sm->fhat[t],
                                        emb[sm->idxs[t >> 5] * 32 + (t & 31)]);
        } else {
            for (int t = tid; t < N * 32; t += 512)
                sm->zbuf[t] = emb[sm->idxs[t >> 5] * 32 + (t & 31)];
            // weights: compute_weight_mat(pn, 16, 16/pn, 0, keys_cubic, True)
            if (tid < 16) {
                const int i = tid;
                double scl_d = 16.0 / (double)pn;
                float inv = (float)(1.0 / scl_d);
                float sf = __fsub_rn(__fmul_rn(__fadd_rn((float)i, 0.5f), inv), 0.5f);
                float tot = 0.0f;
                for (int k = 0; k < pn; k++) {
                    float x = fabsf(__fsub_rn(sf, (float)k));
                    tot = __fadd_rn(tot, keys_w(x));
                }
                for (int k = 0; k < pn; k++) {
                    float x = fabsf(__fsub_rn(sf, (float)k));
                    sm->wu[k * 16 + i] = __fdiv_rn(keys_w(x), tot);
                }
            }
            __syncthreads();
            // pass 1: contract input-h (k ascending) -> tmpf
            const int n1 = 16 * pn * 32;
            for (int t = tid; t < n1; t += 512) {
                int c = t & 31, kw = (t >> 5) % pn, i = (t >> 5) / pn;
                float acc = 0.0f;
                for (int k = 0; k < pn; k++)
                    acc = fmaf(sm->wu[k * 16 + i], sm->zbuf[(k * pn + kw) * 32 + c], acc);
                tmpf[t] = acc;   // layout (i*pn + kw)*32 + c
            }
            __syncthreads();
            // pass 2: contract input-w, then update fhat/frest
            for (int t = tid; t < 8192; t += 512) {
                int c = t & 31, j = (t >> 5) & 15, i = t >> 9;
                float acc = 0.0f;
                for (int k = 0; k < pn; k++)
                    acc = fmaf(sm->wu[k * 16 + j], tmpf[(i * pn + k) * 32 + c], acc);
                sm->fhat[t] = __fadd_rn(sm->fhat[t], acc);
                sm->frest[t] = __fsub_rn(sm->frest[t], acc);
            }
        }

        cluster_sync_();   // peer done with g_key before next-scale overwrite
        __syncthreads();
    }

    // ---------- write output: BHWC -> BCHW ----------
    for (int t = tid; t < 4096; t += 512) {
        int c = rank * 16 + (t >> 8);
        int ij = t & 255;
        out[(b * 32 + c) * 256 + ij] = sm->fhat[ij * 32 + c];
    }
}

// ---------------------------------------------------------------------------
extern "C" void kernel_launch(void* const* d_in, const int* in_sizes, int n_in,
                              void* d_out, int out_size) {
    (void)in_sizes; (void)n_in; (void)out_size;
    const float* f = (const float*)d_in[0];     // [64,32,16,16] f32
    const float* emb = (const float*)d_in[1];   // [4096,32] f32
    float* out = (float*)d_out;                 // [64,32,16,16] f32

    static int smem_set = 0;
    if (!smem_set) {
        cudaFuncSetAttribute(vq_main_kernel,
                             cudaFuncAttributeMaxDynamicSharedMemorySize,
                             (int)sizeof(SMem));
        smem_set = 1;
    }

    vq_prep_kernel<<<16, 256>>>(emb);
    vq_main_kernel<<<128, 512, sizeof(SMem)>>>(f, emb, out);
}

// round 14
// speedup vs baseline: 1.1421x; 1.0039x over previous
#include <cuda_runtime.h>
#include <cuda_bf16.h>
#include <cstdint>

// ---------------------------------------------------------------------------
// Multi-scale residual VQ (VectorQuantizer2): B=64, C=32, H=W=16, vocab=4096
// scales pn = {1,2,3,4,5,6,8,10,13,16}
//
// One 2-CTA cluster per batch image; codebook split 2048/2048 across the pair.
// 512 threads/CTA (16 warps/SM, 4/SMSP). Thread tile: 8 codes x 8 rows = 32
// independent fma.rn.f32x2 chains (64 acc regs). Per channel k: 2 LDS.128
// (8 consecutive codes = 4 natural f32x2 pairs) + 4 broadcast LDS.128 (8 rows
// of prebuilt {-2z,-2z}) + 32 FFMA2 -> smem crossbar at 75% of the fma pipe
// (R12 was exactly 100%-balanced, capping fma at 26%). 16 warps = 4 code-
// groups x 4 row-groups over 32-row blocks; codebook staged in 1024-code /
// 128 KB smem chunks. Each f32x2 half reproduces the reference's sequential
// ascending-c FMA chain bit-exactly. Argmin: in-thread ascending min-of-8,
// redux+ballot (lane order == code order), smem atomicMin on (biased-dist,
// idx) u64 keys, cross-CTA merge via global scratch + barrier.cluster.
// Smem 229.5 KB via aliasing: idxs->bkey, wu->zsq (disjoint lifetimes).
// ---------------------------------------------------------------------------

#define NSCALES 10
__device__ __constant__ int c_pns[NSCALES] = {1, 2, 3, 4, 5, 6, 8, 10, 13, 16};

// device scratch (static globals -- no allocation)
__device__ float g_ecb[32 * 4096];               // [c][code] transposed codebook
__device__ float g_esq[4096];                    // ||e||^2 (rounded squares, seq sum)
__device__ unsigned long long g_key[64 * 512];   // per-batch, per-rank best keys

// ---------------- shared memory (229504 B) ----------------
struct SMem {
    float echunk[32 * 1024];             // 128 KB [k][code]; aliased as tmpf scratch
    unsigned long long zdupb[32 * 32];   // 8 KB   [k][row-in-32-block] {-2z,-2z}
    float frest[8192];                   // [h][w][c]
    float fhat[8192];                    // [h][w][c]
    float zbuf[5408];                    // z rows / gathered codes (N<=169 non-last)
    unsigned long long bkey[256];        // running best; aliased as idxs after merge
    float zsq[256];                      // per-row ||z||^2; aliased as wu after dist
};

__device__ __forceinline__ void cluster_sync_() {
    asm volatile("barrier.cluster.arrive.aligned;\n\t"
                 "barrier.cluster.wait.aligned;\n" ::: "memory");
}

__device__ __forceinline__ void ffma2(unsigned long long& acc,
                                      unsigned long long a, unsigned long long b) {
    asm("fma.rn.f32x2 %0, %1, %2, %0;" : "+l"(acc) : "l"(a), "l"(b));
}
__device__ __forceinline__ unsigned long long pack2(float lo, float hi) {
    unsigned long long d;
    unsigned a = __float_as_uint(lo), b = __float_as_uint(hi);
    asm("mov.b64 %0, {%1, %2};" : "=l"(d) : "r"(a), "r"(b));
    return d;
}
__device__ __forceinline__ void unpack2(unsigned long long v, float& lo, float& hi) {
    unsigned a, b;
    asm("mov.b64 {%0, %1}, %2;" : "=r"(a), "=r"(b) : "l"(v));
    lo = __uint_as_float(a);
    hi = __uint_as_float(b);
}
__device__ __forceinline__ unsigned redux_min_u32(unsigned v) {
    unsigned r;
    asm("redux.sync.min.u32 %0, %1, 0xffffffff;" : "=r"(r) : "r"(v));
    return r;
}

// jax _fill_keys_cubic_kernel (a = -0.5), each op rounded separately
__device__ __forceinline__ float keys_w(float x) {
    float w;
    if (x < 1.0f) {
        float t = __fmul_rn(1.5f, x);
        t = __fsub_rn(t, 2.5f);
        t = __fmul_rn(t, x);
        t = __fmul_rn(t, x);
        w = __fadd_rn(t, 1.0f);
    } else if (x < 2.0f) {
        float t = __fmul_rn(-0.5f, x);
        t = __fadd_rn(t, 2.5f);
        t = __fmul_rn(t, x);
        t = __fsub_rn(t, 4.0f);
        t = __fmul_rn(t, x);
        w = __fadd_rn(t, 2.0f);
    } else {
        w = 0.0f;
    }
    return w;
}

// ---------------------------------------------------------------------------
// prep: transpose codebook to [c][code] + esq
// ---------------------------------------------------------------------------
__global__ void vq_prep_kernel(const float* __restrict__ emb) {
    int j = blockIdx.x * blockDim.x + threadIdx.x;
    if (j >= 4096) return;
    float acc = 0.0f;
#pragma unroll
    for (int c = 0; c < 32; c++) {
        float x = emb[j * 32 + c];
        acc = __fadd_rn(acc, __fmul_rn(x, x));
        g_ecb[c * 4096 + j] = x;
    }
    g_esq[j] = acc;
}

// ---------------------------------------------------------------------------
// main kernel: one cluster (2 CTAs) per batch image, 512 threads
// ---------------------------------------------------------------------------
extern "C" __global__ void __cluster_dims__(2, 1, 1) __launch_bounds__(512, 1)
vq_main_kernel(const float* __restrict__ f, const float* __restrict__ emb,
               float* __restrict__ out) {
    extern __shared__ char smem_raw[];
    SMem* sm = reinterpret_cast<SMem*>(smem_raw);

    const int tid = threadIdx.x;
    const int lane = tid & 31;
    const int wid = tid >> 5;
    const int b = blockIdx.x >> 1;
    const int rank = blockIdx.x & 1;
    const int cgrp = wid & 3;    // code group: 4 x 256 codes = 1024
    const int rgrp = wid >> 2;   // row group:  4 x 8 rows = 32-row block

    // init: frest = transpose(f) (BCHW -> HWC), fhat = 0
    for (int t = tid; t < 8192; t += 512) {
        int c = t & 31;
        int ij = t >> 5;
        sm->frest[t] = f[(b * 32 + c) * 256 + ij];
        sm->fhat[t] = 0.0f;
    }
    __syncthreads();

    float* tmpf = sm->echunk;                              // scratch alias
    float* wu = sm->zsq;                                   // alias: dead after dist
    int* idxs = reinterpret_cast<int*>(sm->bkey);          // alias: dead after merge

    for (int si = 0; si < NSCALES; si++) {
        const int pn = c_pns[si];
        const int N = pn * pn;
        const bool last = (si == NSCALES - 1);

        // ---------- z = area pool of frest (last scale: z aliases frest) ----------
        if (!last) {
            const int n1 = pn * 16 * 32;
            for (int t = tid; t < n1; t += 512) {
                int c = t & 31, w = (t >> 5) & 15, p = t >> 9;
                int sh = (p * 16) / pn;
                int eh = ((p + 1) * 16 + pn - 1) / pn;
                float wt = (float)(1.0 / (double)(eh - sh));
                float acc = 0.0f;
                for (int h = sh; h < eh; h++)
                    acc = fmaf(wt, sm->frest[(h * 16 + w) * 32 + c], acc);
                tmpf[t] = acc;
            }
            __syncthreads();
            const int n2 = N * 32;
            for (int t = tid; t < n2; t += 512) {
                int c = t & 31, q = (t >> 5) % pn, p = (t >> 5) / pn;
                int sw = (q * 16) / pn;
                int ew = ((q + 1) * 16 + pn - 1) / pn;
                float wt = (float)(1.0 / (double)(ew - sw));
                float acc = 0.0f;
                for (int w = sw; w < ew; w++)
                    acc = fmaf(wt, tmpf[p * 512 + w * 32 + c], acc);
                sm->zbuf[t] = acc;
            }
            __syncthreads();
        }
        const float* zp = last ? sm->frest : sm->zbuf;

        // ---------- zsq (rounded squares, sequential ascending sum) ----------
        if (tid < N) {
            float acc = 0.0f;
            for (int c = 0; c < 32; c++) {
                float z = zp[tid * 32 + c];
                acc = __fadd_rn(acc, __fmul_rn(z, z));
            }
            sm->zsq[tid] = acc;
        }
        for (int t = tid; t < N; t += 512) sm->bkey[t] = 0xFFFFFFFFFFFFFFFFull;
        __syncthreads();

        // ---------- distance + argmin over this CTA's 2048-code half ----------
        const int nblk = (N + 31) >> 5;
        for (int chunk = 0; chunk < 2; chunk++) {
            const int cbase = rank * 2048 + chunk * 1024;
            // stage 1024 codes x 32 ch (128 KB), [k][code]
            {
                float4* dst = reinterpret_cast<float4*>(sm->echunk);
                for (int t = tid; t < 8192; t += 512) {
                    int k = t >> 8, j4 = t & 255;
                    dst[k * 256 + j4] = *reinterpret_cast<const float4*>(
                        &g_ecb[k * 4096 + cbase + j4 * 4]);
                }
            }
            const int c0 = cgrp * 256 + lane * 8;   // my 8 codes within chunk
            float eqv[8];
            {
                float4 eA = *reinterpret_cast<const float4*>(g_esq + cbase + c0);
                float4 eB = *reinterpret_cast<const float4*>(g_esq + cbase + c0 + 4);
                eqv[0] = eA.x; eqv[1] = eA.y; eqv[2] = eA.z; eqv[3] = eA.w;
                eqv[4] = eB.x; eqv[5] = eB.y; eqv[6] = eB.z; eqv[7] = eB.w;
            }
            __syncthreads();

            for (int blk = 0; blk < nblk; blk++) {
                // build {-2z,-2z} for this 32-row block, layout [k][row]
                {
                    int k = tid >> 5, r = tid & 31;          // entry 0 of 2
                    int row = blk * 32 + r;
                    if (row >= N) row = N - 1;
                    float m = __fmul_rn(-2.0f, zp[row * 32 + k]);   // exact *(-2)
                    sm->zdupb[k * 32 + r] = pack2(m, m);
                    k += 16;                                  // entry 1
                    m = __fmul_rn(-2.0f, zp[row * 32 + k]);
                    sm->zdupb[k * 32 + r] = pack2(m, m);
                }
                __syncthreads();

                unsigned long long acc[32];   // [pair p][row i] = acc[p*8+i]
#pragma unroll
                for (int i = 0; i < 32; i++) acc[i] = 0ull;

#pragma unroll
                for (int k = 0; k < 32; k++) {
                    // 8 consecutive codes = 4 natural f32x2 pairs
                    const ulonglong2* ep = reinterpret_cast<const ulonglong2*>(
                        &sm->echunk[k * 1024 + c0]);
                    ulonglong2 e01 = ep[0];   // pairs {c0,c0+1},{c0+2,c0+3}
                    ulonglong2 e23 = ep[1];   // pairs {c0+4,c0+5},{c0+6,c0+7}
                    // 8 rows of {-2z,-2z} (broadcast)
                    const ulonglong2* zb = reinterpret_cast<const ulonglong2*>(
                        &sm->zdupb[k * 32 + rgrp * 8]);
                    ulonglong2 z01 = zb[0];
                    ulonglong2 z23 = zb[1];
                    ffma2(acc[0],  z01.x, e01.x);
                    ffma2(acc[8],  z01.x, e01.y);
                    ffma2(acc[16], z01.x, e23.x);
                    ffma2(acc[24], z01.x, e23.y);
                    ffma2(acc[1],  z01.y, e01.x);
                    ffma2(acc[9],  z01.y, e01.y);
                    ffma2(acc[17], z01.y, e23.x);
                    ffma2(acc[25], z01.y, e23.y);
                    ffma2(acc[2],  z23.x, e01.x);
                    ffma2(acc[10], z23.x, e01.y);
                    ffma2(acc[18], z23.x, e23.x);
                    ffma2(acc[26], z23.x, e23.y);
                    ffma2(acc[3],  z23.y, e01.x);
                    ffma2(acc[11], z23.y, e01.y);
                    ffma2(acc[19], z23.y, e23.x);
                    ffma2(acc[27], z23.y, e23.y);
                    ulonglong2 z45 = zb[2];
                    ulonglong2 z67 = zb[3];
                    ffma2(acc[4],  z45.x, e01.x);
                    ffma2(acc[12], z45.x, e01.y);
                    ffma2(acc[20], z45.x, e23.x);
                    ffma2(acc[28], z45.x, e23.y);
                    ffma2(acc[5],  z45.y, e01.x);
                    ffma2(acc[13], z45.y, e01.y);
                    ffma2(acc[21], z45.y, e23.x);
                    ffma2(acc[29], z45.y, e23.y);
                    ffma2(acc[6],  z67.x, e01.x);
                    ffma2(acc[14], z67.x, e01.y);
                    ffma2(acc[22], z67.x, e23.x);
                    ffma2(acc[30], z67.x, e23.y);
                    ffma2(acc[7],  z67.y, e01.x);
                    ffma2(acc[15], z67.y, e01.y);
                    ffma2(acc[23], z67.y, e23.x);
                    ffma2(acc[31], z67.y, e23.y);
                }

                // epilogue: 8 rows, best of my 8 codes -> warp -> smem atomicMin
#pragma unroll
                for (int i = 0; i < 8; i++) {
                    int row = blk * 32 + rgrp * 8 + i;
                    if (row < N) {
                        int rowc = row;                    // already < N
                        float zs = sm->zsq[rowc];
                        float d[8];
                        unpack2(acc[i],      d[0], d[1]);  // codes c0..c0+1
                        unpack2(acc[8 + i],  d[2], d[3]);  // c0+2..c0+3
                        unpack2(acc[16 + i], d[4], d[5]);  // c0+4..c0+5
                        unpack2(acc[24 + i], d[6], d[7]);  // c0+6..c0+7
                        float best;
                        int bi = 0;
                        best = __fadd_rn(__fadd_rn(zs, eqv[0]), d[0]);
#pragma unroll
                        for (int j = 1; j < 8; j++) {
                            float dj = __fadd_rn(__fadd_rn(zs, eqv[j]), d[j]);
                            if (dj < best) { best = dj; bi = j; }
                        }
                        unsigned ub = __float_as_uint(best);
                        ub = (ub & 0x80000000u) ? ~ub : (ub ^ 0x80000000u);
                        unsigned mn = redux_min_u32(ub);
                        unsigned msk = __ballot_sync(0xffffffffu, ub == mn);
                        if (lane == (__ffs(msk) - 1))
                            atomicMin(&sm->bkey[rowc],
                                      ((unsigned long long)ub << 32) |
                                          (unsigned)(cbase + c0 + bi));
                    }
                }
                __syncthreads();   // block done before zdupb rebuild
            }
            __syncthreads();   // all atomics done; echunk free for restage
        }

        // ---------- merge halves across the CTA pair ----------
        for (int t = tid; t < N; t += 512)
            g_key[(b << 9) + (rank << 8) + t] = sm->bkey[t];
        cluster_sync_();   // release/acquire covers gmem at cluster scope
        for (int t = tid; t < N; t += 512) {
            unsigned long long k0 = g_key[(b << 9) + t];
            unsigned long long k1 = g_key[(b << 9) + 256 + t];
            idxs[t] = (int)((k0 < k1 ? k0 : k1) & 0xFFFFFFFFu);   // bkey now dead
        }
        __syncthreads();

        // ---------- gather h = emb[idx], upsample, update ----------
        if (last) {
            for (int t = tid; t < 8192; t += 512)
                sm->fhat[t] = __fadd_rn(sm->fhat[t],
                                        emb[idxs[t >> 5] * 32 + (t & 31)]);
        } else {
            for (int t = tid; t < N * 32; t += 512)
                sm->zbuf[t] = emb[idxs[t >> 5] * 32 + (t & 31)];
            // weights: compute_weight_mat(pn, 16, 16/pn, 0, keys_cubic, True)
            // (wu aliases zsq -- zsq is dead after the distance pass)
            if (tid < 16) {
                const int i = tid;
                double scl_d = 16.0 / (double)pn;
                float inv = (float)(1.0 / scl_d);
                float sf = __fsub_rn(__fmul_rn(__fadd_rn((float)i, 0.5f), inv), 0.5f);
                float tot = 0.0f;
                for (int k = 0; k < pn; k++) {
                    float x = fabsf(__fsub_rn(sf, (float)k));
                    tot = __fadd_rn(tot, keys_w(x));
                }
                for (int k = 0; k < pn; k++) {
                    float x = fabsf(__fsub_rn(sf, (float)k));
                    wu[k * 16 + i] = __fdiv_rn(keys_w(x), tot);
                }
            }
            __syncthreads();
            // pass 1: contract input-h (k ascending) -> tmpf
            const int n1 = 16 * pn * 32;
            for (int t = tid; t < n1; t += 512) {
                int c = t & 31, kw = (t >> 5) % pn, i = (t >> 5) / pn;
                float acc = 0.0f;
                for (int k = 0; k < pn; k++)
                    acc = fmaf(wu[k * 16 + i], sm->zbuf[(k * pn + kw) * 32 + c], acc);
                tmpf[t] = acc;   // layout (i*pn + kw)*32 + c
            }
            __syncthreads();
            // pass 2: contract input-w, then update fhat/frest
            for (int t = tid; t < 8192; t += 512) {
                int c = t & 31, j = (t >> 5) & 15, i = t >> 9;
                float acc = 0.0f;
                for (int k = 0; k < pn; k++)
                    acc = fmaf(wu[k * 16 + j], tmpf[(i * pn + k) * 32 + c], acc);
                sm->fhat[t] = __fadd_rn(sm->fhat[t], acc);
                sm->frest[t] = __fsub_rn(sm->frest[t], acc);
            }
        }

        cluster_sync_();   // peer done with g_key before next-scale overwrite
        __syncthreads();
    }

    // ---------- write output: BHWC -> BCHW ----------
    for (int t = tid; t < 4096; t += 512) {
        int c = rank * 16 + (t >> 8);
        int ij = t & 255;
        out[(b * 32 + c) * 256 + ij] = sm->fhat[ij * 32 + c];
    }
}

// ---------------------------------------------------------------------------
extern "C" void kernel_launch(void* const* d_in, const int* in_sizes, int n_in,
                              void* d_out, int out_size) {
    (void)in_sizes; (void)n_in; (void)out_size;
    const float* f = (const float*)d_in[0];     // [64,32,16,16] f32
    const float* emb = (const float*)d_in[1];   // [4096,32] f32
    float* out = (float*)d_out;                 // [64,32,16,16] f32

    static int smem_set = 0;
    if (!smem_set) {
        cudaFuncSetAttribute(vq_main_kernel,
                             cudaFuncAttributeMaxDynamicSharedMemorySize,
                             (int)sizeof(SMem));
        smem_set = 1;
    }

    vq_prep_kernel<<<16, 256>>>(emb);
    vq_main_kernel<<<128, 512, sizeof(SMem)>>>(f, emb, out);
}